// round 16
// baseline (speedup 1.0000x reference)
#include <cuda_runtime.h>
#include <cuda_fp16.h>
#include <math.h>
#include <stdint.h>

// Problem constants (fixed by setup_inputs)
#define B_SZ    8
#define S_LEN   1024
#define NHEADS  16
#define HDIM    64
#define HIDDEN  1024
#define WIN     64
#define NTOK    (B_SZ * S_LEN)          // 8192
#define QKV_N   (3 * HIDDEN)            // 3072

// ---------------------------------------------------------------------------
// Scratch (device globals — no allocation allowed in kernel_launch)
// ---------------------------------------------------------------------------
__device__ __half g_qh[(size_t)NTOK * QKV_N];   // 48 MB: qkv hi (rope'd q,k)
__device__ __half g_ql[(size_t)NTOK * QKV_N];   // lo (only q block written)

__device__ __half g_hh[(size_t)NTOK * HIDDEN];
__device__ __half g_hl[(size_t)NTOK * HIDDEN];
__device__ __half g_wqh[(size_t)QKV_N * HIDDEN];
__device__ __half g_woh[(size_t)HIDDEN * HIDDEN];
__device__ __half g_ah[(size_t)NTOK * HIDDEN];

__device__ float2 g_rope[S_LEN * 32];   // (cos, sin) per (t, d)

// ---------------------------------------------------------------------------
// rope table
// ---------------------------------------------------------------------------
__global__ void rope_table_kernel()
{
    int idx = blockIdx.x * blockDim.x + threadIdx.x;
    if (idx >= S_LEN * 32) return;
    int t = idx >> 5, d = idx & 31;
    float inv = powf(10000.0f, -(float)d * (1.0f / 32.0f));
    float sn, cs;
    sincosf((float)t * inv, &sn, &cs);
    g_rope[idx] = make_float2(cs, sn);
}

// ---------------------------------------------------------------------------
// fp32 -> fp16 hi/lo split (lo may be null -> hi-only convert)
// ---------------------------------------------------------------------------
__global__ void split_f16_kernel(const float* __restrict__ x,
                                 __half* __restrict__ hi,
                                 __half* __restrict__ lo, int n)
{
    int i = (blockIdx.x * blockDim.x + threadIdx.x) * 4;
    if (i >= n) return;
    float4 v = *(const float4*)(x + i);
    __half h0 = __float2half(v.x);
    __half h1 = __float2half(v.y);
    __half h2 = __float2half(v.z);
    __half h3 = __float2half(v.w);
    *(__half2*)(hi + i)     = __halves2half2(h0, h1);
    *(__half2*)(hi + i + 2) = __halves2half2(h2, h3);
    if (lo) {
        *(__half2*)(lo + i) = __halves2half2(
            __float2half(v.x - __half2float(h0)),
            __float2half(v.y - __half2float(h1)));
        *(__half2*)(lo + i + 2) = __halves2half2(
            __float2half(v.z - __half2float(h2)),
            __float2half(v.w - __half2float(h3)));
    }
}

// ---------------------------------------------------------------------------
// PTX helpers
// ---------------------------------------------------------------------------
__device__ __forceinline__ uint32_t smem_u32(const void* p) {
    uint32_t a;
    asm("{ .reg .u64 t; cvta.to.shared.u64 t, %1; cvt.u32.u64 %0, t; }"
        : "=r"(a) : "l"(p));
    return a;
}

#define CP_ASYNC16(dst, src) \
    asm volatile("cp.async.cg.shared.global [%0], [%1], 16;" \
                 :: "r"(dst), "l"(src) : "memory")
#define CP_COMMIT()  asm volatile("cp.async.commit_group;" ::: "memory")
#define CP_WAIT0()   asm volatile("cp.async.wait_group 0;" ::: "memory")

#define LDMX4(r0, r1, r2, r3, a) \
    asm volatile("ldmatrix.sync.aligned.m8n8.x4.shared.b16 {%0,%1,%2,%3}, [%4];" \
                 : "=r"(r0), "=r"(r1), "=r"(r2), "=r"(r3) : "r"(a))

#define LDMX2(r0, r1, a) \
    asm volatile("ldmatrix.sync.aligned.m8n8.x2.shared.b16 {%0,%1}, [%2];" \
                 : "=r"(r0), "=r"(r1) : "r"(a))

#define LDMX2T(r0, r1, a) \
    asm volatile("ldmatrix.sync.aligned.m8n8.x2.trans.shared.b16 {%0,%1}, [%2];" \
                 : "=r"(r0), "=r"(r1) : "r"(a))

// fp16 inputs, fp32 accumulate
#define MMA16816H(d, a, b) \
    asm volatile("mma.sync.aligned.m16n8k16.row.col.f32.f16.f16.f32 " \
                 "{%0,%1,%2,%3}, {%4,%5,%6,%7}, {%8,%9}, {%0,%1,%2,%3};" \
                 : "+f"((d)[0]), "+f"((d)[1]), "+f"((d)[2]), "+f"((d)[3]) \
                 : "r"((a)[0]), "r"((a)[1]), "r"((a)[2]), "r"((a)[3]), \
                   "r"((b)[0]), "r"((b)[1]))

__device__ __forceinline__ uint32_t pack_hi2(float x, float y) {
    __half2 p = __halves2half2(__float2half(x), __float2half(y));
    return *(uint32_t*)&p;
}
__device__ __forceinline__ uint32_t pack_lo2(float x, float y) {
    float hx = __half2float(__float2half(x));
    float hy = __half2float(__float2half(y));
    __half2 p = __halves2half2(__float2half(x - hx), __float2half(y - hy));
    return *(uint32_t*)&p;
}

// ---------------------------------------------------------------------------
// fp16 GEMM via mma.sync: C = (Ah [+ Al]) @ Bh^T
// Correction term (Al·Bh) only for tiles with bn < n_corr.
// QKV path (Chi != null): RoPE + 1/8 q-scale fused into epilogue; lo written
// only for the Q block (cols < 1024). Out path (Chi == null): fp32 C.
// Persistent CTAs, 4 warps of 64x64.
// ---------------------------------------------------------------------------
#define KC        32
#define TSTRIDE   40
#define TILE_B    (128 * TSTRIDE * 2)   // 10240 B
#define BUF_B     (3 * TILE_B)          // Ah, Al, Bh slots
#define GSMEM     (2 * BUF_B)           // 61440 B

__global__ __launch_bounds__(128, 2) void gemm_f16_kernel(
    const __half* __restrict__ Ah, const __half* __restrict__ Al,
    const __half* __restrict__ Bh,
    const float2* __restrict__ rope,
    float* __restrict__ C,
    __half* __restrict__ Chi, __half* __restrict__ Clo,
    int M, int N, int K, int ntiles, int n_corr)
{
    extern __shared__ char smem[];
    const uint32_t sbase = smem_u32(smem);

    const int tid  = threadIdx.x;
    const int wid  = tid >> 5;
    const int lane = tid & 31;
    const int m0 = (wid & 1) * 64;
    const int n0 = (wid >> 1) * 64;
    const int nb = N >> 7;

    const int quad = lane >> 3, lrow = lane & 7;
    const int a_off = ((quad & 1) * 8 + lrow) * TSTRIDE + (quad >> 1) * 8;
    const int b_off = ((quad >> 1) * 8 + lrow) * TSTRIDE + (quad & 1) * 8;
    const int g = lane >> 2, tg = lane & 3;
    const int NCH = K / KC;

    for (int tile = blockIdx.x; tile < ntiles; tile += gridDim.x) {
        const int bm = (tile / nb) * 128;
        const int bn = (tile % nb) * 128;
        const bool corr = (Al != nullptr) && (bn < n_corr);

        auto stage_one = [&](int buf, int slot, const __half* src, int r0, int ch) {
            const __half* s = src + (size_t)r0 * K + ch * KC;
            uint32_t db = sbase + buf * BUF_B + slot * TILE_B;
            #pragma unroll
            for (int i = 0; i < 4; i++) {
                int u = tid + 128 * i;          // 0..511
                int row = u >> 2, c16 = u & 3;
                CP_ASYNC16(db + row * (TSTRIDE * 2) + c16 * 16,
                           s + (size_t)row * K + c16 * 8);
            }
        };
        auto stage_async = [&](int buf, int ch) {
            stage_one(buf, 0, Ah, bm, ch);
            if (corr) stage_one(buf, 1, Al, bm, ch);
            stage_one(buf, 2, Bh, bn, ch);
        };

        float acc[4][8][4] = {};
        float accc[4][8][4] = {};   // correction accumulators (fp32)

        stage_async(0, 0);
        CP_COMMIT();

        for (int c = 0; c < NCH; c++) {
            const int buf = c & 1;
            CP_WAIT0();
            __syncthreads();
            if (c + 1 < NCH) { stage_async((c + 1) & 1, c + 1); CP_COMMIT(); }

            const uint32_t base = sbase + buf * BUF_B;
            #pragma unroll
            for (int kk = 0; kk < 2; kk++) {
                uint32_t ah[4][4], bh[8][2];
                #pragma unroll
                for (int mi = 0; mi < 4; mi++) {
                    uint32_t ea = ((m0 + mi * 16) * TSTRIDE + kk * 16 + a_off) * 2;
                    LDMX4(ah[mi][0], ah[mi][1], ah[mi][2], ah[mi][3], base + ea);
                }
                #pragma unroll
                for (int np = 0; np < 4; np++) {
                    uint32_t eb = ((n0 + np * 16) * TSTRIDE + kk * 16 + b_off) * 2;
                    LDMX4(bh[2*np][0], bh[2*np][1], bh[2*np+1][0], bh[2*np+1][1],
                          base + 2 * TILE_B + eb);
                }
                #pragma unroll
                for (int mi = 0; mi < 4; mi++)
                    #pragma unroll
                    for (int ni = 0; ni < 8; ni++)
                        MMA16816H(acc[mi][ni], ah[mi], bh[ni]);
                if (corr) {
                    uint32_t al[4][4];
                    #pragma unroll
                    for (int mi = 0; mi < 4; mi++) {
                        uint32_t ea = ((m0 + mi * 16) * TSTRIDE + kk * 16 + a_off) * 2;
                        LDMX4(al[mi][0], al[mi][1], al[mi][2], al[mi][3],
                              base + TILE_B + ea);
                    }
                    #pragma unroll
                    for (int mi = 0; mi < 4; mi++)
                        #pragma unroll
                        for (int ni = 0; ni < 8; ni++)
                            MMA16816H(accc[mi][ni], al[mi], bh[ni]);
                }
            }
            __syncthreads();
        }

        if (corr) {
            #pragma unroll
            for (int mi = 0; mi < 4; mi++)
                #pragma unroll
                for (int ni = 0; ni < 8; ni++)
                    #pragma unroll
                    for (int e = 0; e < 4; e++)
                        acc[mi][ni][e] += accc[mi][ni][e];
        }

        if (Chi) {
            // QKV path: fused RoPE (q,k blocks) + 1/8 scale (q block)
            const int cb = bn + n0;                  // 64-aligned = one head
            const bool do_rope = cb < 2 * HIDDEN;    // q or k
            const bool store_lo = cb < HIDDEN;       // q only
            const float qsc = (cb < HIDDEN) ? 0.125f : 1.0f;
            #pragma unroll
            for (int mi = 0; mi < 4; mi++) {
                const int r0 = bm + m0 + mi * 16 + g;
                #pragma unroll
                for (int np = 0; np < 4; np++) {
                    float x1[4], x2[4];
                    #pragma unroll
                    for (int e = 0; e < 4; e++) {
                        x1[e] = acc[mi][np][e];
                        x2[e] = acc[mi][np + 4][e];
                    }
                    if (do_rope) {
                        #pragma unroll
                        for (int rr = 0; rr < 2; rr++) {
                            const int t = (r0 + rr * 8) & (S_LEN - 1);
                            #pragma unroll
                            for (int e = 0; e < 2; e++) {
                                const int d = np * 8 + tg * 2 + e;
                                float2 cs = rope[t * 32 + d];
                                const int ix = rr * 2 + e;
                                float a = x1[ix], b = x2[ix];
                                x1[ix] = (a * cs.x - b * cs.y) * qsc;
                                x2[ix] = (b * cs.x + a * cs.y) * qsc;
                            }
                        }
                    }
                    const int col = cb + np * 8 + tg * 2;
                    size_t i0 = (size_t)r0 * N + col;
                    size_t i1 = i0 + 8 * (size_t)N;
                    *(uint32_t*)&Chi[i0]      = pack_hi2(x1[0], x1[1]);
                    *(uint32_t*)&Chi[i0 + 32] = pack_hi2(x2[0], x2[1]);
                    *(uint32_t*)&Chi[i1]      = pack_hi2(x1[2], x1[3]);
                    *(uint32_t*)&Chi[i1 + 32] = pack_hi2(x2[2], x2[3]);
                    if (store_lo) {
                        *(uint32_t*)&Clo[i0]      = pack_lo2(x1[0], x1[1]);
                        *(uint32_t*)&Clo[i0 + 32] = pack_lo2(x2[0], x2[1]);
                        *(uint32_t*)&Clo[i1]      = pack_lo2(x1[2], x1[3]);
                        *(uint32_t*)&Clo[i1 + 32] = pack_lo2(x2[2], x2[3]);
                    }
                }
            }
        } else {
            #pragma unroll
            for (int mi = 0; mi < 4; mi++) {
                const int row = bm + m0 + mi * 16 + g;
                #pragma unroll
                for (int ni = 0; ni < 8; ni++) {
                    const int col = bn + n0 + ni * 8 + tg * 2;
                    *(float2*)&C[(size_t)row * N + col] =
                        make_float2(acc[mi][ni][0], acc[mi][ni][1]);
                    *(float2*)&C[(size_t)(row + 8) * N + col] =
                        make_float2(acc[mi][ni][2], acc[mi][ni][3]);
                }
            }
        }
        __syncthreads();
    }
}

// ---------------------------------------------------------------------------
// Sliding-window attention via fp16 HMMA.
// Inputs already rope'd + scaled; staging is pure copies.
// S = (Qh+Ql)·Kh^T ; O = (Ph+Pl)·Vh ; output stored hi-only.
// ---------------------------------------------------------------------------
#define ASTR   72
#define KROWS  256
#define O_QH   0
#define O_QL   (128 * ASTR)
#define O_KH   (2 * 128 * ASTR)
#define O_VH   (O_KH + KROWS * ASTR)
#define ATT_SMEM_BYTES ((O_VH + KROWS * ASTR) * 2)   // 110592

__global__ __launch_bounds__(256, 1) void attn_mma_kernel(
    const __half* __restrict__ qh, const __half* __restrict__ ql,
    __half* __restrict__ out_h)
{
    extern __shared__ __half smb[];
    const uint32_t sb = smem_u32(smb);

    const int bx = blockIdx.x;          // qt + 8*(h + 16*b)
    const int qt = bx & 7;
    const int h  = (bx >> 3) & 15;
    const int b  = bx >> 7;
    const int q0 = qt * 128;
    const int kbase = q0 - 64;
    const size_t tok_base = (size_t)b * S_LEN;
    const int koff = h * HDIM;

    const int tid = threadIdx.x;

    // ---- stage Q (hi + lo, pure copy; rope+scale already applied) ----
    for (int idx = tid; idx < 128 * 8; idx += 256) {
        int row = idx >> 3, c8 = (idx & 7) << 3;
        size_t off = (tok_base + q0 + row) * QKV_N + koff + c8;
        int e = row * ASTR + c8;
        *(uint4*)&smb[O_QH + e] = *(const uint4*)(qh + off);
        *(uint4*)&smb[O_QL + e] = *(const uint4*)(ql + off);
    }
    // ---- stage K (hi only, pure copy, zero-fill OOB) ----
    for (int idx = tid; idx < KROWS * 8; idx += 256) {
        int row = idx >> 3, c8 = (idx & 7) << 3;
        int kg = kbase + row;
        uint4 v = make_uint4(0, 0, 0, 0);
        if (kg >= 0 && kg < S_LEN)
            v = *(const uint4*)(qh + (tok_base + kg) * QKV_N + HIDDEN + koff + c8);
        *(uint4*)&smb[O_KH + row * ASTR + c8] = v;
    }
    // ---- stage V (hi only, pure copy, zero-fill OOB) ----
    for (int idx = tid; idx < KROWS * 8; idx += 256) {
        int row = idx >> 3, c8 = (idx & 7) << 3;
        int kg = kbase + row;
        uint4 v = make_uint4(0, 0, 0, 0);
        if (kg >= 0 && kg < S_LEN)
            v = *(const uint4*)(qh + (tok_base + kg) * QKV_N + 2 * HIDDEN + koff + c8);
        *(uint4*)&smb[O_VH + row * ASTR + c8] = v;
    }
    __syncthreads();

    // ---- per-warp compute ----
    const int w = tid >> 5, lane = tid & 31;
    const int quad = lane >> 3, lrow = lane & 7;
    const int a_off = ((quad & 1) * 8 + lrow) * ASTR + (quad >> 1) * 8;
    const int b_off = lrow * ASTR + (quad & 1) * 8;
    const int qrow0 = 16 * w;

    float S[18][4];
    #pragma unroll
    for (int jj = 0; jj < 18; jj++)
        S[jj][0] = S[jj][1] = S[jj][2] = S[jj][3] = 0.f;

    #pragma unroll
    for (int kk = 0; kk < 4; kk++) {
        uint32_t qhf[4], qlf[4];
        uint32_t ea = sb + 2u * (O_QH + qrow0 * ASTR + kk * 16 + a_off);
        uint32_t el = sb + 2u * (O_QL + qrow0 * ASTR + kk * 16 + a_off);
        LDMX4(qhf[0], qhf[1], qhf[2], qhf[3], ea);
        LDMX4(qlf[0], qlf[1], qlf[2], qlf[3], el);
        #pragma unroll
        for (int jc = 0; jc < 3; jc++) {
            uint32_t kh[6][2];
            #pragma unroll
            for (int j6 = 0; j6 < 6; j6++) {
                int kr = qrow0 + (jc * 6 + j6) * 8;
                LDMX2(kh[j6][0], kh[j6][1], sb + 2u * (O_KH + kr * ASTR + kk * 16 + b_off));
            }
            #pragma unroll
            for (int j6 = 0; j6 < 6; j6++)
                MMA16816H(S[jc * 6 + j6], qhf, kh[j6]);
            #pragma unroll
            for (int j6 = 0; j6 < 6; j6++)
                MMA16816H(S[jc * 6 + j6], qlf, kh[j6]);
        }
    }

    // ---- mask + softmax ----
    const int g = lane >> 2, tg = lane & 3;
    const int qg = q0 + qrow0 + g;
    #pragma unroll
    for (int jj = 0; jj < 18; jj++) {
        int col = kbase + qrow0 + jj * 8 + 2 * tg;
        #pragma unroll
        for (int e = 0; e < 2; e++) {
            int c = col + e;
            bool okc = (c >= 0) && (c < S_LEN);
            int d0 = c - qg;
            if (!(okc && d0 >= -WIN && d0 <= WIN)) S[jj][e] = -1e30f;
            int d1 = d0 - 8;
            if (!(okc && d1 >= -WIN && d1 <= WIN)) S[jj][2 + e] = -1e30f;
        }
    }
    float m0 = -1e30f, m1 = -1e30f;
    #pragma unroll
    for (int jj = 0; jj < 18; jj++) {
        m0 = fmaxf(m0, fmaxf(S[jj][0], S[jj][1]));
        m1 = fmaxf(m1, fmaxf(S[jj][2], S[jj][3]));
    }
    m0 = fmaxf(m0, __shfl_xor_sync(0xffffffffu, m0, 1));
    m0 = fmaxf(m0, __shfl_xor_sync(0xffffffffu, m0, 2));
    m1 = fmaxf(m1, __shfl_xor_sync(0xffffffffu, m1, 1));
    m1 = fmaxf(m1, __shfl_xor_sync(0xffffffffu, m1, 2));
    float s0 = 0.f, s1 = 0.f;
    #pragma unroll
    for (int jj = 0; jj < 18; jj++) {
        S[jj][0] = __expf(S[jj][0] - m0); s0 += S[jj][0];
        S[jj][1] = __expf(S[jj][1] - m0); s0 += S[jj][1];
        S[jj][2] = __expf(S[jj][2] - m1); s1 += S[jj][2];
        S[jj][3] = __expf(S[jj][3] - m1); s1 += S[jj][3];
    }
    s0 += __shfl_xor_sync(0xffffffffu, s0, 1);
    s0 += __shfl_xor_sync(0xffffffffu, s0, 2);
    s1 += __shfl_xor_sync(0xffffffffu, s1, 1);
    s1 += __shfl_xor_sync(0xffffffffu, s1, 2);
    const float r0 = 1.0f / s0, r1 = 1.0f / s1;
    #pragma unroll
    for (int jj = 0; jj < 18; jj++) {
        S[jj][0] *= r0; S[jj][1] *= r0; S[jj][2] *= r1; S[jj][3] *= r1;
    }

    // ---- O = (Ph+Pl) Vh : 9 kt tiles (144 keys) ----
    float O[8][4];
    #pragma unroll
    for (int ni = 0; ni < 8; ni++)
        O[ni][0] = O[ni][1] = O[ni][2] = O[ni][3] = 0.f;

    const int vrow = lane & 15;
    #pragma unroll
    for (int kt = 0; kt < 9; kt++) {
        const float* sA = S[2 * kt];
        const float* sB = S[2 * kt + 1];
        uint32_t ph[4], pl[4];
        ph[0] = pack_hi2(sA[0], sA[1]); pl[0] = pack_lo2(sA[0], sA[1]);
        ph[1] = pack_hi2(sA[2], sA[3]); pl[1] = pack_lo2(sA[2], sA[3]);
        ph[2] = pack_hi2(sB[0], sB[1]); pl[2] = pack_lo2(sB[0], sB[1]);
        ph[3] = pack_hi2(sB[2], sB[3]); pl[3] = pack_lo2(sB[2], sB[3]);
        const int vr = qrow0 + kt * 16 + vrow;
        #pragma unroll
        for (int nc = 0; nc < 2; nc++) {
            uint32_t vh[4][2];
            #pragma unroll
            for (int n4 = 0; n4 < 4; n4++) {
                int ni = nc * 4 + n4;
                LDMX2T(vh[n4][0], vh[n4][1], sb + 2u * (O_VH + vr * ASTR + ni * 8));
            }
            #pragma unroll
            for (int n4 = 0; n4 < 4; n4++)
                MMA16816H(O[nc * 4 + n4], ph, vh[n4]);
            #pragma unroll
            for (int n4 = 0; n4 < 4; n4++)
                MMA16816H(O[nc * 4 + n4], pl, vh[n4]);
        }
    }

    // ---- store O hi-only (out-projection is single-term) ----
    #pragma unroll
    for (int ni = 0; ni < 8; ni++) {
        const int col = koff + ni * 8 + 2 * tg;
        size_t i0 = (tok_base + qg) * HIDDEN + col;
        size_t i1 = (tok_base + qg + 8) * HIDDEN + col;
        *(uint32_t*)&out_h[i0] = pack_hi2(O[ni][0], O[ni][1]);
        *(uint32_t*)&out_h[i1] = pack_hi2(O[ni][2], O[ni][3]);
    }
}

// ---------------------------------------------------------------------------
// Launch
// ---------------------------------------------------------------------------
extern "C" void kernel_launch(void* const* d_in, const int* in_sizes, int n_in,
                              void* d_out, int out_size)
{
    const float* hidden = nullptr;
    const float* wqkv = nullptr;
    const float* wo = nullptr;
    for (int i = 0; i < n_in; i++) {
        if (in_sizes[i] == NTOK * HIDDEN)            hidden = (const float*)d_in[i];
        else if (in_sizes[i] == QKV_N * HIDDEN)      wqkv   = (const float*)d_in[i];
        else if (in_sizes[i] == HIDDEN * HIDDEN)     wo     = (const float*)d_in[i];
    }

    __half *qh, *ql, *hh, *hl, *wqh, *woh, *ah;
    float2* rope;
    cudaGetSymbolAddress((void**)&qh,  g_qh);
    cudaGetSymbolAddress((void**)&ql,  g_ql);
    cudaGetSymbolAddress((void**)&hh,  g_hh);
    cudaGetSymbolAddress((void**)&hl,  g_hl);
    cudaGetSymbolAddress((void**)&wqh, g_wqh);
    cudaGetSymbolAddress((void**)&woh, g_woh);
    cudaGetSymbolAddress((void**)&ah,  g_ah);
    cudaGetSymbolAddress((void**)&rope, g_rope);

    cudaFuncSetAttribute(gemm_f16_kernel,
                         cudaFuncAttributeMaxDynamicSharedMemorySize, GSMEM);
    cudaFuncSetAttribute(attn_mma_kernel,
                         cudaFuncAttributeMaxDynamicSharedMemorySize, ATT_SMEM_BYTES);

    // 0) rope table + splits (weights: hi only)
    rope_table_kernel<<<(S_LEN * 32 + 255) / 256, 256>>>();
    {
        int n;
        n = NTOK * HIDDEN;
        split_f16_kernel<<<(n / 4 + 255) / 256, 256>>>(hidden, hh, hl, n);
        n = QKV_N * HIDDEN;
        split_f16_kernel<<<(n / 4 + 255) / 256, 256>>>(wqkv, wqh, nullptr, n);
        n = HIDDEN * HIDDEN;
        split_f16_kernel<<<(n / 4 + 255) / 256, 256>>>(wo, woh, nullptr, n);
    }

    // 1) QKV projection: correction only for Q block; RoPE+scale in epilogue
    gemm_f16_kernel<<<296, 128, GSMEM>>>(
        hh, hl, wqh, rope, nullptr, qh, ql,
        NTOK, QKV_N, HIDDEN, (NTOK / 128) * (QKV_N / 128), HIDDEN);

    // 2) sliding-window attention (pure-copy staging)
    attn_mma_kernel<<<B_SZ * NHEADS * (S_LEN / 128), 256, ATT_SMEM_BYTES>>>(
        qh, ql, ah);

    // 3) output projection (single-term) -> fp32 d_out
    gemm_f16_kernel<<<296, 128, GSMEM>>>(
        ah, nullptr, woh, rope, (float*)d_out, nullptr, nullptr,
        NTOK, HIDDEN, HIDDEN, (NTOK / 128) * (HIDDEN / 128), 0);
}

// round 17
// speedup vs baseline: 1.9533x; 1.9533x over previous
#include <cuda_runtime.h>
#include <cuda_fp16.h>
#include <math.h>
#include <stdint.h>

// Problem constants (fixed by setup_inputs)
#define B_SZ    8
#define S_LEN   1024
#define NHEADS  16
#define HDIM    64
#define HIDDEN  1024
#define WIN     64
#define NTOK    (B_SZ * S_LEN)          // 8192
#define QKV_N   (3 * HIDDEN)            // 3072

// ---------------------------------------------------------------------------
// Scratch (device globals — no allocation allowed in kernel_launch)
// ---------------------------------------------------------------------------
__device__ __half g_qh[(size_t)NTOK * QKV_N];   // 48 MB: qkv hi (rope'd q,k)
__device__ __half g_ql[(size_t)NTOK * QKV_N];   // lo (only q block written)

__device__ __half g_hh[(size_t)NTOK * HIDDEN];
__device__ __half g_hl[(size_t)NTOK * HIDDEN];
__device__ __half g_wqh[(size_t)QKV_N * HIDDEN];
__device__ __half g_woh[(size_t)HIDDEN * HIDDEN];
__device__ __half g_ah[(size_t)NTOK * HIDDEN];

__device__ float2 g_rope[S_LEN * 32];   // (cos, sin) per (t, d)

// ---------------------------------------------------------------------------
// rope table
// ---------------------------------------------------------------------------
__global__ void rope_table_kernel()
{
    int idx = blockIdx.x * blockDim.x + threadIdx.x;
    if (idx >= S_LEN * 32) return;
    int t = idx >> 5, d = idx & 31;
    float inv = powf(10000.0f, -(float)d * (1.0f / 32.0f));
    float sn, cs;
    sincosf((float)t * inv, &sn, &cs);
    g_rope[idx] = make_float2(cs, sn);
}

// ---------------------------------------------------------------------------
// fp32 -> fp16 hi/lo split (lo may be null -> hi-only convert)
// ---------------------------------------------------------------------------
__global__ void split_f16_kernel(const float* __restrict__ x,
                                 __half* __restrict__ hi,
                                 __half* __restrict__ lo, int n)
{
    int i = (blockIdx.x * blockDim.x + threadIdx.x) * 4;
    if (i >= n) return;
    float4 v = *(const float4*)(x + i);
    __half h0 = __float2half(v.x);
    __half h1 = __float2half(v.y);
    __half h2 = __float2half(v.z);
    __half h3 = __float2half(v.w);
    *(__half2*)(hi + i)     = __halves2half2(h0, h1);
    *(__half2*)(hi + i + 2) = __halves2half2(h2, h3);
    if (lo) {
        *(__half2*)(lo + i) = __halves2half2(
            __float2half(v.x - __half2float(h0)),
            __float2half(v.y - __half2float(h1)));
        *(__half2*)(lo + i + 2) = __halves2half2(
            __float2half(v.z - __half2float(h2)),
            __float2half(v.w - __half2float(h3)));
    }
}

// ---------------------------------------------------------------------------
// PTX helpers
// ---------------------------------------------------------------------------
__device__ __forceinline__ uint32_t smem_u32(const void* p) {
    uint32_t a;
    asm("{ .reg .u64 t; cvta.to.shared.u64 t, %1; cvt.u32.u64 %0, t; }"
        : "=r"(a) : "l"(p));
    return a;
}

#define CP_ASYNC16(dst, src) \
    asm volatile("cp.async.cg.shared.global [%0], [%1], 16;" \
                 :: "r"(dst), "l"(src) : "memory")
#define CP_COMMIT()  asm volatile("cp.async.commit_group;" ::: "memory")
#define CP_WAIT0()   asm volatile("cp.async.wait_group 0;" ::: "memory")

#define LDMX4(r0, r1, r2, r3, a) \
    asm volatile("ldmatrix.sync.aligned.m8n8.x4.shared.b16 {%0,%1,%2,%3}, [%4];" \
                 : "=r"(r0), "=r"(r1), "=r"(r2), "=r"(r3) : "r"(a))

#define LDMX2(r0, r1, a) \
    asm volatile("ldmatrix.sync.aligned.m8n8.x2.shared.b16 {%0,%1}, [%2];" \
                 : "=r"(r0), "=r"(r1) : "r"(a))

#define LDMX2T(r0, r1, a) \
    asm volatile("ldmatrix.sync.aligned.m8n8.x2.trans.shared.b16 {%0,%1}, [%2];" \
                 : "=r"(r0), "=r"(r1) : "r"(a))

// fp16 inputs, fp32 accumulate
#define MMA16816H(d, a, b) \
    asm volatile("mma.sync.aligned.m16n8k16.row.col.f32.f16.f16.f32 " \
                 "{%0,%1,%2,%3}, {%4,%5,%6,%7}, {%8,%9}, {%0,%1,%2,%3};" \
                 : "+f"((d)[0]), "+f"((d)[1]), "+f"((d)[2]), "+f"((d)[3]) \
                 : "r"((a)[0]), "r"((a)[1]), "r"((a)[2]), "r"((a)[3]), \
                   "r"((b)[0]), "r"((b)[1]))

__device__ __forceinline__ uint32_t pack_hi2(float x, float y) {
    __half2 p = __halves2half2(__float2half(x), __float2half(y));
    return *(uint32_t*)&p;
}
__device__ __forceinline__ uint32_t pack_lo2(float x, float y) {
    float hx = __half2float(__float2half(x));
    float hy = __half2float(__float2half(y));
    __half2 p = __halves2half2(__float2half(x - hx), __float2half(y - hy));
    return *(uint32_t*)&p;
}

// ---------------------------------------------------------------------------
// fp16 GEMM via mma.sync: C = (Ah [+ Al]) @ Bh^T
// Correction term (Al·Bh) accumulated DIRECTLY into acc (no extra register
// arrays — R16's accc[] caused spills). Correction only for bn < n_corr.
// QKV path (Chi != null): RoPE + 1/8 q-scale fused into epilogue; lo written
// only for the Q block. Out path (Chi == null): fp32 C.
// ---------------------------------------------------------------------------
#define KC        32
#define TSTRIDE   40
#define TILE_B    (128 * TSTRIDE * 2)   // 10240 B
#define BUF_B     (3 * TILE_B)          // Ah, Al, Bh slots
#define GSMEM     (2 * BUF_B)           // 61440 B

__global__ __launch_bounds__(128, 2) void gemm_f16_kernel(
    const __half* __restrict__ Ah, const __half* __restrict__ Al,
    const __half* __restrict__ Bh,
    const float2* __restrict__ rope,
    float* __restrict__ C,
    __half* __restrict__ Chi, __half* __restrict__ Clo,
    int M, int N, int K, int ntiles, int n_corr)
{
    extern __shared__ char smem[];
    const uint32_t sbase = smem_u32(smem);

    const int tid  = threadIdx.x;
    const int wid  = tid >> 5;
    const int lane = tid & 31;
    const int m0 = (wid & 1) * 64;
    const int n0 = (wid >> 1) * 64;
    const int nb = N >> 7;

    const int quad = lane >> 3, lrow = lane & 7;
    const int a_off = ((quad & 1) * 8 + lrow) * TSTRIDE + (quad >> 1) * 8;
    const int b_off = ((quad >> 1) * 8 + lrow) * TSTRIDE + (quad & 1) * 8;
    const int g = lane >> 2, tg = lane & 3;
    const int NCH = K / KC;

    for (int tile = blockIdx.x; tile < ntiles; tile += gridDim.x) {
        const int bm = (tile / nb) * 128;
        const int bn = (tile % nb) * 128;
        const bool corr = (Al != nullptr) && (bn < n_corr);

        auto stage_one = [&](int buf, int slot, const __half* src, int r0, int ch) {
            const __half* s = src + (size_t)r0 * K + ch * KC;
            uint32_t db = sbase + buf * BUF_B + slot * TILE_B;
            #pragma unroll
            for (int i = 0; i < 4; i++) {
                int u = tid + 128 * i;          // 0..511
                int row = u >> 2, c16 = u & 3;
                CP_ASYNC16(db + row * (TSTRIDE * 2) + c16 * 16,
                           s + (size_t)row * K + c16 * 8);
            }
        };
        auto stage_async = [&](int buf, int ch) {
            stage_one(buf, 0, Ah, bm, ch);
            if (corr) stage_one(buf, 1, Al, bm, ch);
            stage_one(buf, 2, Bh, bn, ch);
        };

        float acc[4][8][4] = {};

        stage_async(0, 0);
        CP_COMMIT();

        for (int c = 0; c < NCH; c++) {
            const int buf = c & 1;
            CP_WAIT0();
            __syncthreads();
            if (c + 1 < NCH) { stage_async((c + 1) & 1, c + 1); CP_COMMIT(); }

            const uint32_t base = sbase + buf * BUF_B;
            #pragma unroll
            for (int kk = 0; kk < 2; kk++) {
                uint32_t ah[4][4], bh[8][2];
                #pragma unroll
                for (int mi = 0; mi < 4; mi++) {
                    uint32_t ea = ((m0 + mi * 16) * TSTRIDE + kk * 16 + a_off) * 2;
                    LDMX4(ah[mi][0], ah[mi][1], ah[mi][2], ah[mi][3], base + ea);
                }
                #pragma unroll
                for (int np = 0; np < 4; np++) {
                    uint32_t eb = ((n0 + np * 16) * TSTRIDE + kk * 16 + b_off) * 2;
                    LDMX4(bh[2*np][0], bh[2*np][1], bh[2*np+1][0], bh[2*np+1][1],
                          base + 2 * TILE_B + eb);
                }
                #pragma unroll
                for (int mi = 0; mi < 4; mi++)
                    #pragma unroll
                    for (int ni = 0; ni < 8; ni++)
                        MMA16816H(acc[mi][ni], ah[mi], bh[ni]);
                if (corr) {
                    // reuse ah registers for Al fragments; accumulate into acc
                    #pragma unroll
                    for (int mi = 0; mi < 4; mi++) {
                        uint32_t ea = ((m0 + mi * 16) * TSTRIDE + kk * 16 + a_off) * 2;
                        LDMX4(ah[mi][0], ah[mi][1], ah[mi][2], ah[mi][3],
                              base + TILE_B + ea);
                    }
                    #pragma unroll
                    for (int mi = 0; mi < 4; mi++)
                        #pragma unroll
                        for (int ni = 0; ni < 8; ni++)
                            MMA16816H(acc[mi][ni], ah[mi], bh[ni]);
                }
            }
            __syncthreads();
        }

        if (Chi) {
            // QKV path: fused RoPE (q,k blocks) + 1/8 scale (q block)
            const int cb = bn + n0;                  // 64-aligned = one head
            const bool do_rope = cb < 2 * HIDDEN;    // q or k
            const bool store_lo = cb < HIDDEN;       // q only
            const float qsc = (cb < HIDDEN) ? 0.125f : 1.0f;
            #pragma unroll
            for (int mi = 0; mi < 4; mi++) {
                const int r0 = bm + m0 + mi * 16 + g;
                #pragma unroll
                for (int np = 0; np < 4; np++) {
                    float x1[4], x2[4];
                    #pragma unroll
                    for (int e = 0; e < 4; e++) {
                        x1[e] = acc[mi][np][e];
                        x2[e] = acc[mi][np + 4][e];
                    }
                    if (do_rope) {
                        #pragma unroll
                        for (int rr = 0; rr < 2; rr++) {
                            const int t = (r0 + rr * 8) & (S_LEN - 1);
                            #pragma unroll
                            for (int e = 0; e < 2; e++) {
                                const int d = np * 8 + tg * 2 + e;
                                float2 cs = rope[t * 32 + d];
                                const int ix = rr * 2 + e;
                                float a = x1[ix], b = x2[ix];
                                x1[ix] = (a * cs.x - b * cs.y) * qsc;
                                x2[ix] = (b * cs.x + a * cs.y) * qsc;
                            }
                        }
                    }
                    const int col = cb + np * 8 + tg * 2;
                    size_t i0 = (size_t)r0 * N + col;
                    size_t i1 = i0 + 8 * (size_t)N;
                    *(uint32_t*)&Chi[i0]      = pack_hi2(x1[0], x1[1]);
                    *(uint32_t*)&Chi[i0 + 32] = pack_hi2(x2[0], x2[1]);
                    *(uint32_t*)&Chi[i1]      = pack_hi2(x1[2], x1[3]);
                    *(uint32_t*)&Chi[i1 + 32] = pack_hi2(x2[2], x2[3]);
                    if (store_lo) {
                        *(uint32_t*)&Clo[i0]      = pack_lo2(x1[0], x1[1]);
                        *(uint32_t*)&Clo[i0 + 32] = pack_lo2(x2[0], x2[1]);
                        *(uint32_t*)&Clo[i1]      = pack_lo2(x1[2], x1[3]);
                        *(uint32_t*)&Clo[i1 + 32] = pack_lo2(x2[2], x2[3]);
                    }
                }
            }
        } else {
            #pragma unroll
            for (int mi = 0; mi < 4; mi++) {
                const int row = bm + m0 + mi * 16 + g;
                #pragma unroll
                for (int ni = 0; ni < 8; ni++) {
                    const int col = bn + n0 + ni * 8 + tg * 2;
                    *(float2*)&C[(size_t)row * N + col] =
                        make_float2(acc[mi][ni][0], acc[mi][ni][1]);
                    *(float2*)&C[(size_t)(row + 8) * N + col] =
                        make_float2(acc[mi][ni][2], acc[mi][ni][3]);
                }
            }
        }
        __syncthreads();
    }
}

// ---------------------------------------------------------------------------
// Sliding-window attention via fp16 HMMA (unchanged from R16 — staging is
// pure copies, S = (Qh+Ql)·Kh^T, O = (Ph+Pl)·Vh, hi-only output).
// ---------------------------------------------------------------------------
#define ASTR   72
#define KROWS  256
#define O_QH   0
#define O_QL   (128 * ASTR)
#define O_KH   (2 * 128 * ASTR)
#define O_VH   (O_KH + KROWS * ASTR)
#define ATT_SMEM_BYTES ((O_VH + KROWS * ASTR) * 2)   // 110592

__global__ __launch_bounds__(256, 1) void attn_mma_kernel(
    const __half* __restrict__ qh, const __half* __restrict__ ql,
    __half* __restrict__ out_h)
{
    extern __shared__ __half smb[];
    const uint32_t sb = smem_u32(smb);

    const int bx = blockIdx.x;          // qt + 8*(h + 16*b)
    const int qt = bx & 7;
    const int h  = (bx >> 3) & 15;
    const int b  = bx >> 7;
    const int q0 = qt * 128;
    const int kbase = q0 - 64;
    const size_t tok_base = (size_t)b * S_LEN;
    const int koff = h * HDIM;

    const int tid = threadIdx.x;

    // ---- stage Q (hi + lo, pure copy) ----
    for (int idx = tid; idx < 128 * 8; idx += 256) {
        int row = idx >> 3, c8 = (idx & 7) << 3;
        size_t off = (tok_base + q0 + row) * QKV_N + koff + c8;
        int e = row * ASTR + c8;
        *(uint4*)&smb[O_QH + e] = *(const uint4*)(qh + off);
        *(uint4*)&smb[O_QL + e] = *(const uint4*)(ql + off);
    }
    // ---- stage K (hi only, pure copy, zero-fill OOB) ----
    for (int idx = tid; idx < KROWS * 8; idx += 256) {
        int row = idx >> 3, c8 = (idx & 7) << 3;
        int kg = kbase + row;
        uint4 v = make_uint4(0, 0, 0, 0);
        if (kg >= 0 && kg < S_LEN)
            v = *(const uint4*)(qh + (tok_base + kg) * QKV_N + HIDDEN + koff + c8);
        *(uint4*)&smb[O_KH + row * ASTR + c8] = v;
    }
    // ---- stage V (hi only, pure copy, zero-fill OOB) ----
    for (int idx = tid; idx < KROWS * 8; idx += 256) {
        int row = idx >> 3, c8 = (idx & 7) << 3;
        int kg = kbase + row;
        uint4 v = make_uint4(0, 0, 0, 0);
        if (kg >= 0 && kg < S_LEN)
            v = *(const uint4*)(qh + (tok_base + kg) * QKV_N + 2 * HIDDEN + koff + c8);
        *(uint4*)&smb[O_VH + row * ASTR + c8] = v;
    }
    __syncthreads();

    // ---- per-warp compute ----
    const int w = tid >> 5, lane = tid & 31;
    const int quad = lane >> 3, lrow = lane & 7;
    const int a_off = ((quad & 1) * 8 + lrow) * ASTR + (quad >> 1) * 8;
    const int b_off = lrow * ASTR + (quad & 1) * 8;
    const int qrow0 = 16 * w;

    float S[18][4];
    #pragma unroll
    for (int jj = 0; jj < 18; jj++)
        S[jj][0] = S[jj][1] = S[jj][2] = S[jj][3] = 0.f;

    #pragma unroll
    for (int kk = 0; kk < 4; kk++) {
        uint32_t qhf[4], qlf[4];
        uint32_t ea = sb + 2u * (O_QH + qrow0 * ASTR + kk * 16 + a_off);
        uint32_t el = sb + 2u * (O_QL + qrow0 * ASTR + kk * 16 + a_off);
        LDMX4(qhf[0], qhf[1], qhf[2], qhf[3], ea);
        LDMX4(qlf[0], qlf[1], qlf[2], qlf[3], el);
        #pragma unroll
        for (int jc = 0; jc < 3; jc++) {
            uint32_t kh[6][2];
            #pragma unroll
            for (int j6 = 0; j6 < 6; j6++) {
                int kr = qrow0 + (jc * 6 + j6) * 8;
                LDMX2(kh[j6][0], kh[j6][1], sb + 2u * (O_KH + kr * ASTR + kk * 16 + b_off));
            }
            #pragma unroll
            for (int j6 = 0; j6 < 6; j6++)
                MMA16816H(S[jc * 6 + j6], qhf, kh[j6]);
            #pragma unroll
            for (int j6 = 0; j6 < 6; j6++)
                MMA16816H(S[jc * 6 + j6], qlf, kh[j6]);
        }
    }

    // ---- mask + softmax ----
    const int g = lane >> 2, tg = lane & 3;
    const int qg = q0 + qrow0 + g;
    #pragma unroll
    for (int jj = 0; jj < 18; jj++) {
        int col = kbase + qrow0 + jj * 8 + 2 * tg;
        #pragma unroll
        for (int e = 0; e < 2; e++) {
            int c = col + e;
            bool okc = (c >= 0) && (c < S_LEN);
            int d0 = c - qg;
            if (!(okc && d0 >= -WIN && d0 <= WIN)) S[jj][e] = -1e30f;
            int d1 = d0 - 8;
            if (!(okc && d1 >= -WIN && d1 <= WIN)) S[jj][2 + e] = -1e30f;
        }
    }
    float m0 = -1e30f, m1 = -1e30f;
    #pragma unroll
    for (int jj = 0; jj < 18; jj++) {
        m0 = fmaxf(m0, fmaxf(S[jj][0], S[jj][1]));
        m1 = fmaxf(m1, fmaxf(S[jj][2], S[jj][3]));
    }
    m0 = fmaxf(m0, __shfl_xor_sync(0xffffffffu, m0, 1));
    m0 = fmaxf(m0, __shfl_xor_sync(0xffffffffu, m0, 2));
    m1 = fmaxf(m1, __shfl_xor_sync(0xffffffffu, m1, 1));
    m1 = fmaxf(m1, __shfl_xor_sync(0xffffffffu, m1, 2));
    float s0 = 0.f, s1 = 0.f;
    #pragma unroll
    for (int jj = 0; jj < 18; jj++) {
        S[jj][0] = __expf(S[jj][0] - m0); s0 += S[jj][0];
        S[jj][1] = __expf(S[jj][1] - m0); s0 += S[jj][1];
        S[jj][2] = __expf(S[jj][2] - m1); s1 += S[jj][2];
        S[jj][3] = __expf(S[jj][3] - m1); s1 += S[jj][3];
    }
    s0 += __shfl_xor_sync(0xffffffffu, s0, 1);
    s0 += __shfl_xor_sync(0xffffffffu, s0, 2);
    s1 += __shfl_xor_sync(0xffffffffu, s1, 1);
    s1 += __shfl_xor_sync(0xffffffffu, s1, 2);
    const float r0 = 1.0f / s0, r1 = 1.0f / s1;
    #pragma unroll
    for (int jj = 0; jj < 18; jj++) {
        S[jj][0] *= r0; S[jj][1] *= r0; S[jj][2] *= r1; S[jj][3] *= r1;
    }

    // ---- O = (Ph+Pl) Vh : 9 kt tiles (144 keys) ----
    float O[8][4];
    #pragma unroll
    for (int ni = 0; ni < 8; ni++)
        O[ni][0] = O[ni][1] = O[ni][2] = O[ni][3] = 0.f;

    const int vrow = lane & 15;
    #pragma unroll
    for (int kt = 0; kt < 9; kt++) {
        const float* sA = S[2 * kt];
        const float* sB = S[2 * kt + 1];
        uint32_t ph[4], pl[4];
        ph[0] = pack_hi2(sA[0], sA[1]); pl[0] = pack_lo2(sA[0], sA[1]);
        ph[1] = pack_hi2(sA[2], sA[3]); pl[1] = pack_lo2(sA[2], sA[3]);
        ph[2] = pack_hi2(sB[0], sB[1]); pl[2] = pack_lo2(sB[0], sB[1]);
        ph[3] = pack_hi2(sB[2], sB[3]); pl[3] = pack_lo2(sB[2], sB[3]);
        const int vr = qrow0 + kt * 16 + vrow;
        #pragma unroll
        for (int nc = 0; nc < 2; nc++) {
            uint32_t vh[4][2];
            #pragma unroll
            for (int n4 = 0; n4 < 4; n4++) {
                int ni = nc * 4 + n4;
                LDMX2T(vh[n4][0], vh[n4][1], sb + 2u * (O_VH + vr * ASTR + ni * 8));
            }
            #pragma unroll
            for (int n4 = 0; n4 < 4; n4++)
                MMA16816H(O[nc * 4 + n4], ph, vh[n4]);
            #pragma unroll
            for (int n4 = 0; n4 < 4; n4++)
                MMA16816H(O[nc * 4 + n4], pl, vh[n4]);
        }
    }

    // ---- store O hi-only (out-projection is single-term) ----
    #pragma unroll
    for (int ni = 0; ni < 8; ni++) {
        const int col = koff + ni * 8 + 2 * tg;
        size_t i0 = (tok_base + qg) * HIDDEN + col;
        size_t i1 = (tok_base + qg + 8) * HIDDEN + col;
        *(uint32_t*)&out_h[i0] = pack_hi2(O[ni][0], O[ni][1]);
        *(uint32_t*)&out_h[i1] = pack_hi2(O[ni][2], O[ni][3]);
    }
}

// ---------------------------------------------------------------------------
// Launch
// ---------------------------------------------------------------------------
extern "C" void kernel_launch(void* const* d_in, const int* in_sizes, int n_in,
                              void* d_out, int out_size)
{
    const float* hidden = nullptr;
    const float* wqkv = nullptr;
    const float* wo = nullptr;
    for (int i = 0; i < n_in; i++) {
        if (in_sizes[i] == NTOK * HIDDEN)            hidden = (const float*)d_in[i];
        else if (in_sizes[i] == QKV_N * HIDDEN)      wqkv   = (const float*)d_in[i];
        else if (in_sizes[i] == HIDDEN * HIDDEN)     wo     = (const float*)d_in[i];
    }

    __half *qh, *ql, *hh, *hl, *wqh, *woh, *ah;
    float2* rope;
    cudaGetSymbolAddress((void**)&qh,  g_qh);
    cudaGetSymbolAddress((void**)&ql,  g_ql);
    cudaGetSymbolAddress((void**)&hh,  g_hh);
    cudaGetSymbolAddress((void**)&hl,  g_hl);
    cudaGetSymbolAddress((void**)&wqh, g_wqh);
    cudaGetSymbolAddress((void**)&woh, g_woh);
    cudaGetSymbolAddress((void**)&ah,  g_ah);
    cudaGetSymbolAddress((void**)&rope, g_rope);

    cudaFuncSetAttribute(gemm_f16_kernel,
                         cudaFuncAttributeMaxDynamicSharedMemorySize, GSMEM);
    cudaFuncSetAttribute(attn_mma_kernel,
                         cudaFuncAttributeMaxDynamicSharedMemorySize, ATT_SMEM_BYTES);

    // 0) rope table + splits (weights: hi only)
    rope_table_kernel<<<(S_LEN * 32 + 255) / 256, 256>>>();
    {
        int n;
        n = NTOK * HIDDEN;
        split_f16_kernel<<<(n / 4 + 255) / 256, 256>>>(hidden, hh, hl, n);
        n = QKV_N * HIDDEN;
        split_f16_kernel<<<(n / 4 + 255) / 256, 256>>>(wqkv, wqh, nullptr, n);
        n = HIDDEN * HIDDEN;
        split_f16_kernel<<<(n / 4 + 255) / 256, 256>>>(wo, woh, nullptr, n);
    }

    // 1) QKV projection: correction only for Q block; RoPE+scale in epilogue
    gemm_f16_kernel<<<296, 128, GSMEM>>>(
        hh, hl, wqh, rope, nullptr, qh, ql,
        NTOK, QKV_N, HIDDEN, (NTOK / 128) * (QKV_N / 128), HIDDEN);

    // 2) sliding-window attention (pure-copy staging)
    attn_mma_kernel<<<B_SZ * NHEADS * (S_LEN / 128), 256, ATT_SMEM_BYTES>>>(
        qh, ql, ah);

    // 3) output projection (single-term) -> fp32 d_out
    gemm_f16_kernel<<<296, 128, GSMEM>>>(
        ah, nullptr, woh, rope, (float*)d_out, nullptr, nullptr,
        NTOK, HIDDEN, HIDDEN, (NTOK / 128) * (HIDDEN / 128), 0);
}